// round 9
// baseline (speedup 1.0000x reference)
#include <cuda_runtime.h>
#include <cuda_bf16.h>
#include <cstdint>

// out[n,R,C,co] = active[n,R/14,C/14] * (bias[co] + sum_{dy,dx,ci} x[n,R+dy,C+dx,ci]*k[dy,dx,ci,co])
// valid 3x3 conv 506x506 -> 504x504, gated per 14x14 tile by mask-block max > 0.5
//
// mma.sync bf16 (fp32 = hi+lo bf16, 3 products), persistent warp-specialized CTAs:
//   1 CTA/SM, 320 threads: warps 0-7 = consumers (tile 16x32, warp = 4 cols x 16 rows),
//   warps 8-9 = producers staging the NEXT tile into a double-buffered X region.
//   A-fragments loaded once per (dy,h), reused across the 3 dx taps.

#define N_IMG 8
#define H_IN  506
#define W_IN  506
#define H_OUT 504
#define W_OUT 504
#define NBH   36
#define NBW   36

#define RT_CNT 32                    // 16-row tiles (rows 496.. guarded)
#define CT_CNT 16                    // 32-col tiles (cols 480.. guarded)
#define TPI    (RT_CNT * CT_CNT)     // 512 tiles per image
#define N_TILES (N_IMG * TPI)        // 4096
#define GRID_CONV 148

#define THREADS 320
#define NCONS   256                  // consumer threads (8 warps)

#define XROWP 35                     // pixel-column pitch (35*9=315 ≡ 3 mod 8)
#define PIXB  144                    // 64B hi(ci0-31) + 64B lo + 16 pad
#define XS_BYTES (18 * XROWP * PIXB) // 90720 per buffer
#define WROWB 144                    // 64B hi ci | 64B lo ci | 16 pad
#define WS_BYTES (9 * 32 * WROWB)    // 41472
#define SMEM_BYTES (2 * XS_BYTES + WS_BYTES)   // 222912

__device__ float g_active[N_IMG * NBH * NBW];

// ------------------------- helpers ------------------------------------------
__device__ __forceinline__ uint32_t smem_u32(const void* p) {
    uint32_t a;
    asm("{ .reg .u64 t; cvta.to.shared.u64 t, %1; cvt.u32.u64 %0, t; }"
        : "=r"(a) : "l"(p));
    return a;
}
__device__ __forceinline__ void sts64(uint32_t a, uint64_t v) {
    asm volatile("st.shared.b64 [%0], %1;" :: "r"(a), "l"(v) : "memory");
}
__device__ __forceinline__ void sts128(uint32_t a, uint32_t r0, uint32_t r1,
                                       uint32_t r2, uint32_t r3) {
    asm volatile("st.shared.v4.b32 [%0], {%1,%2,%3,%4};"
                 :: "r"(a), "r"(r0), "r"(r1), "r"(r2), "r"(r3) : "memory");
}
__device__ __forceinline__ void ldsm4(uint32_t* r, uint32_t addr) {
    asm volatile("ldmatrix.sync.aligned.m8n8.x4.shared.b16 {%0,%1,%2,%3}, [%4];"
                 : "=r"(r[0]), "=r"(r[1]), "=r"(r[2]), "=r"(r[3]) : "r"(addr));
}
__device__ __forceinline__ void mma4(float* d, const uint32_t* a, const uint32_t* b) {
    asm volatile(
        "mma.sync.aligned.m16n8k16.row.col.f32.bf16.bf16.f32 "
        "{%0,%1,%2,%3},{%4,%5,%6,%7},{%8,%9},{%0,%1,%2,%3};"
        : "+f"(d[0]), "+f"(d[1]), "+f"(d[2]), "+f"(d[3])
        : "r"(a[0]), "r"(a[1]), "r"(a[2]), "r"(a[3]), "r"(b[0]), "r"(b[1]));
}
__device__ __forceinline__ unsigned short bf_hi(float f) {
    return __bfloat16_as_ushort(__float2bfloat16_rn(f));
}

// ---------------- kernel 1: mask block max -> active flag -------------------
__global__ void __launch_bounds__(256) mask_kernel(const float* __restrict__ mask) {
    __shared__ float red[256];
    int b = blockIdx.x;
    int n   = b / (NBH * NBW);
    int rem = b % (NBH * NBW);
    int bi = rem / NBW, bj = rem % NBW;
    int tid = threadIdx.x;
    int rr = tid >> 4, cc = tid & 15;
    red[tid] = mask[(n * H_IN + bi * 14 + rr) * W_IN + bj * 14 + cc];
    __syncthreads();
    #pragma unroll
    for (int s = 128; s > 0; s >>= 1) {
        if (tid < s) red[tid] = fmaxf(red[tid], red[tid + s]);
        __syncthreads();
    }
    if (tid == 0) g_active[b] = (red[0] > 0.5f) ? 1.0f : 0.0f;
}

// ---------------- producer: stage one tile's x into buffer ------------------
__device__ __forceinline__ void produce_tile(
    const float* __restrict__ x, uint32_t xb, int n, int R0, int C0, int ptid)
{
    // 18 rows x 34 cols pixels, 32 ci each, hi/lo bf16
    for (int p = ptid; p < 18 * 34; p += 64) {
        int ir = p / 34, ic = p - ir * 34;
        int gr = R0 + ir; if (gr > H_IN - 1) gr = H_IN - 1;
        int gc = C0 + ic; if (gc > W_IN - 1) gc = W_IN - 1;
        const float4* gp = (const float4*)
            (x + (((size_t)n * H_IN + gr) * W_IN + gc) * 32);
        float4 v[8];
        #pragma unroll
        for (int q = 0; q < 8; q++) v[q] = gp[q];
        uint32_t a = xb + (uint32_t)((ir * XROWP + ic) * PIXB);
        #pragma unroll
        for (int o = 0; o < 4; o++) {
            float fv[8] = {v[2*o].x, v[2*o].y, v[2*o].z, v[2*o].w,
                           v[2*o+1].x, v[2*o+1].y, v[2*o+1].z, v[2*o+1].w};
            uint32_t hi[4], lo[4];
            #pragma unroll
            for (int q = 0; q < 4; q++) {
                float f0 = fv[2*q], f1 = fv[2*q+1];
                __nv_bfloat162 h = __floats2bfloat162_rn(f0, f1);
                float r0 = f0 - __bfloat162float(h.x);
                float r1 = f1 - __bfloat162float(h.y);
                __nv_bfloat162 lw = __floats2bfloat162_rn(r0, r1);
                hi[q] = *reinterpret_cast<uint32_t*>(&h);
                lo[q] = *reinterpret_cast<uint32_t*>(&lw);
            }
            sts128(a + o * 16,      hi[0], hi[1], hi[2], hi[3]);
            sts128(a + 64 + o * 16, lo[0], lo[1], lo[2], lo[3]);
        }
    }
}

// ---------------- kernel 2: persistent warp-specialized conv ----------------
__global__ void __launch_bounds__(THREADS, 1) conv_mma_kernel(
    const float* __restrict__ x,
    const float* __restrict__ kern,
    const float* __restrict__ bias,
    float* __restrict__ out)
{
    extern __shared__ char smem[];
    const uint32_t xs0 = smem_u32(smem);
    const uint32_t ws  = xs0 + 2 * XS_BYTES;
    const int tid = threadIdx.x;
    const int wid = tid >> 5;
    const int lid = tid & 31;
    const int bid = blockIdx.x;

    // ---- stage weights once (all threads): ws[tap][co][hi ci | lo ci] ----
    for (int j = tid; j < 2304; j += THREADS) {
        int ciq = j & 7;
        int co  = (j >> 3) & 31;
        int tap = j >> 8;
        int ci  = ciq * 4;
        const float* kp = kern + (tap * 32 + ci) * 32 + co;
        float f0 = kp[0], f1 = kp[32], f2 = kp[64], f3 = kp[96];
        unsigned short h0 = bf_hi(f0), h1 = bf_hi(f1), h2 = bf_hi(f2), h3 = bf_hi(f3);
        unsigned short l0 = bf_hi(f0 - __bfloat162float(__ushort_as_bfloat16(h0)));
        unsigned short l1 = bf_hi(f1 - __bfloat162float(__ushort_as_bfloat16(h1)));
        unsigned short l2 = bf_hi(f2 - __bfloat162float(__ushort_as_bfloat16(h2)));
        unsigned short l3 = bf_hi(f3 - __bfloat162float(__ushort_as_bfloat16(h3)));
        uint64_t hi64 = (uint64_t)h0 | ((uint64_t)h1 << 16)
                      | ((uint64_t)h2 << 32) | ((uint64_t)h3 << 48);
        uint64_t lo64 = (uint64_t)l0 | ((uint64_t)l1 << 16)
                      | ((uint64_t)l2 << 32) | ((uint64_t)l3 << 48);
        uint32_t a = ws + (uint32_t)((tap * 32 + co) * WROWB + ciq * 8);
        sts64(a, hi64);
        sts64(a + 64, lo64);
    }

    // number of tiles this CTA processes
    const int nT = (N_TILES - bid + GRID_CONV - 1) / GRID_CONV;

    if (wid >= 8) {
        // ================= PRODUCER warps (8,9) =================
        const int ptid = tid - NCONS;
        // pre-fill buffer 0 with tile 0
        {
            int t = bid;
            int n = t / TPI, rem = t % TPI;
            produce_tile(x, xs0, n, (rem >> 4) * 16, (rem & 15) * 32, ptid);
        }
        for (int k = 0; k < nT; k++) {
            __syncthreads();          // buf[k&1] now full & handed to consumers
            int k1 = k + 1;
            if (k1 < nT) {
                int t = bid + k1 * GRID_CONV;
                int n = t / TPI, rem = t % TPI;
                produce_tile(x, xs0 + (k1 & 1) * XS_BYTES, n,
                             (rem >> 4) * 16, (rem & 15) * 32, ptid);
            }
        }
        return;
    }

    // ================= CONSUMER warps (0-7) =================
    const int cw = wid * 4;
    const uint32_t baseAoff = (uint32_t)
        (((((lid & 7) + 8 * ((lid >> 3) & 1)) * XROWP) + cw) * PIXB + (lid >> 4) * 16);
    const uint32_t baseB = ws + (uint32_t)
        ((((lid & 7) + ((lid >> 4) << 3)) * WROWB) + ((lid >> 3) & 1) * 16);

    const int n2 = (lid & 3) * 2;
    float2 bv[4];
    #pragma unroll
    for (int nb = 0; nb < 4; nb++)
        bv[nb] = *(const float2*)(bias + nb * 8 + n2);

    for (int k = 0; k < nT; k++) {
        __syncthreads();              // buf[k&1] ready
        const int t   = bid + k * GRID_CONV;
        const int n   = t / TPI;
        const int rem = t % TPI;
        const int R0 = (rem >> 4) * 16;
        const int C0 = (rem & 15) * 32;
        const uint32_t xb = xs0 + (k & 1) * XS_BYTES;
        const uint32_t baseA = xb + baseAoff;

        float d[4][4][4];
        #pragma unroll
        for (int f = 0; f < 4; f++)
            #pragma unroll
            for (int nb = 0; nb < 4; nb++)
                #pragma unroll
                for (int e = 0; e < 4; e++) d[f][nb][e] = 0.0f;

        #pragma unroll 1
        for (int dy = 0; dy < 3; dy++) {
            #pragma unroll 1
            for (int h = 0; h < 2; h++) {
                uint32_t Ah[24], Al[24], Bh[8], Bl[8];
                const uint32_t ao = baseA + (uint32_t)(dy * XROWP * PIXB + h * 32);
                #pragma unroll
                for (int j = 0; j < 6; j++) {
                    ldsm4(Ah + 4 * j, ao + j * PIXB);
                    ldsm4(Al + 4 * j, ao + j * PIXB + 64);
                }
                #pragma unroll
                for (int dx = 0; dx < 3; dx++) {
                    const uint32_t bo = baseB
                        + (uint32_t)((dy * 3 + dx) * (32 * WROWB) + h * 32);
                    ldsm4(Bh,     bo);
                    ldsm4(Bh + 4, bo + 16 * WROWB);
                    ldsm4(Bl,     bo + 64);
                    ldsm4(Bl + 4, bo + 64 + 16 * WROWB);
                    #pragma unroll
                    for (int f = 0; f < 4; f++)
                        #pragma unroll
                        for (int nb = 0; nb < 4; nb++)
                            mma4(d[f][nb], Ah + 4 * (f + dx), Bh + 2 * nb);
                    #pragma unroll
                    for (int f = 0; f < 4; f++)
                        #pragma unroll
                        for (int nb = 0; nb < 4; nb++)
                            mma4(d[f][nb], Ah + 4 * (f + dx), Bl + 2 * nb);
                    #pragma unroll
                    for (int f = 0; f < 4; f++)
                        #pragma unroll
                        for (int nb = 0; nb < 4; nb++)
                            mma4(d[f][nb], Al + 4 * (f + dx), Bh + 2 * nb);
                }
            }
        }

        // ---- epilogue ----
        const int r0 = lid >> 2;
        const int R1 = R0 + r0;
        const int R2 = R1 + 8;
        const bool r2ok = (R2 < H_OUT);
        const int R2c = r2ok ? R2 : H_OUT - 1;
        const float* act1 = g_active + (n * NBH + R1 / 14) * NBW;
        const float* act2 = g_active + (n * NBH + R2c / 14) * NBW;

        #pragma unroll
        for (int f = 0; f < 4; f++) {
            const int C = C0 + cw + f;
            if (C < W_OUT) {
                const int cb = C / 14;
                float fg1 = act1[cb];
                float* o1 = out + (((size_t)n * H_OUT + R1) * W_OUT + C) * 32 + n2;
                #pragma unroll
                for (int nb = 0; nb < 4; nb++) {
                    float2 v;
                    v.x = (d[f][nb][0] + bv[nb].x) * fg1;
                    v.y = (d[f][nb][1] + bv[nb].y) * fg1;
                    *(float2*)(o1 + nb * 8) = v;
                }
                if (r2ok) {
                    float fg2 = act2[cb];
                    float* o2 = out + (((size_t)n * H_OUT + R2) * W_OUT + C) * 32 + n2;
                    #pragma unroll
                    for (int nb = 0; nb < 4; nb++) {
                        float2 v;
                        v.x = (d[f][nb][2] + bv[nb].x) * fg2;
                        v.y = (d[f][nb][3] + bv[nb].y) * fg2;
                        *(float2*)(o2 + nb * 8) = v;
                    }
                }
            }
        }
    }
}

// ---------------------------------------------------------------------------
extern "C" void kernel_launch(void* const* d_in, const int* in_sizes, int n_in,
                              void* d_out, int out_size)
{
    const float* x    = (const float*)d_in[0];
    const float* mask = (const float*)d_in[1];
    const float* kern = (const float*)d_in[2];
    const float* bias = (const float*)d_in[3];
    float* out = (float*)d_out;
    (void)in_sizes; (void)n_in; (void)out_size;

    cudaFuncSetAttribute(conv_mma_kernel,
                         cudaFuncAttributeMaxDynamicSharedMemorySize, SMEM_BYTES);

    mask_kernel<<<N_IMG * NBH * NBW, 256>>>(mask);
    conv_mma_kernel<<<GRID_CONV, THREADS, SMEM_BYTES>>>(x, kern, bias, out);
}